// round 11
// baseline (speedup 1.0000x reference)
#include <cuda_runtime.h>
#include <cuda_fp16.h>
#include <math.h>
#include <stdint.h>

#define B_ 4
#define S_ 2048
#define D_ 1024
#define GC_ 64
#define EPS_ 1e-6f

// GEMM tiling (fp16 operands, f32 accum)
#define BM 128
#define BN 128
#define BK 32
#define ST_ 4
#define SKH 40                            // 32 + 8 pad halves per row
#define STAGE_H (2 * 128 * SKH)           // halves per stage (A + B)
#define STAGE_BYTES (STAGE_H * 2)         // 20480
#define SMEM_DYN (ST_ * STAGE_BYTES)      // 81920

#define BSD ((size_t)B_ * S_ * D_)
#define BSS ((size_t)B_ * S_ * S_)

// ---------------- scratch (device globals: allocation-guard safe) ----------------
static __device__ __align__(256) __half g_Xh [BSD];
static __device__ __align__(256) __half g_Wth[(size_t)4*D_*D_];  // Wq^T|Wk^T|Wv^T|Wo^T
static __device__ __align__(256) __half g_QKVh[3 * BSD];          // Q | K | V (half)
static __device__ __align__(256) __half g_Vth[BSD];
static __device__ __align__(256) __half g_Ph [BSS];               // probs half
static __device__ __align__(256) __half g_Ch [BSD];               // combined half
static __device__ __align__(256) float  g_Sc [BSS];               // scores f32
static __device__ __align__(256) float  g_Cv [BSD];               // conv+LN f32
static __device__ __align__(256) float  g_Ao [BSD];               // attn out f32
static __device__ __align__(256) float  g_bias[3 * D_];

// ---------------- helpers ----------------
__device__ __forceinline__ uint32_t smem_u32(const void* p) {
    uint32_t a;
    asm("{ .reg .u64 t; cvta.to.shared.u64 t, %1; cvt.u32.u64 %0, t; }" : "=r"(a) : "l"(p));
    return a;
}
__device__ __forceinline__ void cpa16(uint32_t s, const void* g) {
    asm volatile("cp.async.cg.shared.global [%0], [%1], 16;" :: "r"(s), "l"(g));
}
#define CP_COMMIT() asm volatile("cp.async.commit_group;" ::: "memory")
#define CP_WAIT2()  asm volatile("cp.async.wait_group 2;"  ::: "memory")

__device__ __forceinline__ void ldsm4(uint32_t* r, uint32_t a) {
    asm volatile("ldmatrix.sync.aligned.m8n8.x4.shared.b16 {%0,%1,%2,%3}, [%4];"
        : "=r"(r[0]), "=r"(r[1]), "=r"(r[2]), "=r"(r[3]) : "r"(a));
}
__device__ __forceinline__ void mma_f16(float* c, const uint32_t* a, const uint32_t* b) {
    asm volatile(
        "mma.sync.aligned.m16n8k16.row.col.f32.f16.f16.f32 "
        "{%0,%1,%2,%3}, {%4,%5,%6,%7}, {%8,%9}, {%0,%1,%2,%3};"
        : "+f"(c[0]), "+f"(c[1]), "+f"(c[2]), "+f"(c[3])
        : "r"(a[0]), "r"(a[1]), "r"(a[2]), "r"(a[3]), "r"(b[0]), "r"(b[1]));
}

// ---------------- fp16 mma GEMM: C = alpha*A@B^T (+bias) (+res) ----------------
// A [M,K], B [N,K] row-major half. 128x128x32 tile, 256 thr, 8 warps (4m x 2n).
// OUTH: 1 -> C is half; 0 -> C is float.
// SPLIT: output columns 1024-segmented into 3 consecutive [M,1024] half buffers.
template <int OUTH, int SPLIT>
__global__ void __launch_bounds__(256, 2) mma_gemm_h(
    const __half* __restrict__ A, const __half* __restrict__ B,
    const float* __restrict__ bias, const float* __restrict__ res,
    void* __restrict__ Cv_, int M, int N, int Kd,
    long long sA, long long sB, long long sC, float alpha)
{
    extern __shared__ __align__(128) __half smemh[];
    const uint32_t smem_base = smem_u32(smemh);

    const int t    = threadIdx.x;
    const int wid  = t >> 5;
    const int lane = t & 31;
    const int g    = lane >> 2;
    const int q    = lane & 3;
    const int wm   = wid & 3;
    const int wn   = wid >> 2;
    const int m0 = blockIdx.y * BM, n0 = blockIdx.x * BN;

    const __half* Ab = A + (long long)blockIdx.z * sA;
    const __half* Bb = B + (long long)blockIdx.z * sB;
    const float*  Rb = res ? res + (long long)blockIdx.z * sC : nullptr;

    float acc[2][8][4];
    #pragma unroll
    for (int i = 0; i < 2; i++)
        #pragma unroll
        for (int j = 0; j < 8; j++)
            #pragma unroll
            for (int k = 0; k < 4; k++) acc[i][j][k] = 0.f;

    const int nk = Kd / BK;

    auto load_stage = [&](int j, int s) {
        const int k0 = j * BK;
        const uint32_t sb = smem_base + (uint32_t)s * STAGE_BYTES;
        #pragma unroll
        for (int i = 0; i < 2; i++) {
            int idx = t + i * 256;
            int row = idx >> 2, c = idx & 3;           // c: 16B chunk (8 halves)
            cpa16(sb + (uint32_t)(row * SKH + c * 8) * 2,
                  Ab + (long long)(m0 + row) * Kd + k0 + c * 8);
        }
        #pragma unroll
        for (int i = 0; i < 2; i++) {
            int idx = t + i * 256;
            int row = idx >> 2, c = idx & 3;
            cpa16(sb + (uint32_t)((128 + row) * SKH + c * 8) * 2,
                  Bb + (long long)(n0 + row) * Kd + k0 + c * 8);
        }
    };

    load_stage(0, 0); CP_COMMIT();
    load_stage(1, 1); CP_COMMIT();
    load_stage(2, 2); CP_COMMIT();

    const int arow = wm * 32;
    const int bcol = wn * 64;

    // ldmatrix lane offsets (bytes)
    const int i8 = lane & 7, l3 = (lane >> 3) & 1, l4 = (lane >> 4) & 1;
    uint32_t offA[2], offB[4];
    #pragma unroll
    for (int mf = 0; mf < 2; mf++) {
        int row = arow + mf * 16 + i8 + l3 * 8;
        offA[mf] = (uint32_t)(row * SKH + l4 * 8) * 2;
    }
    #pragma unroll
    for (int p = 0; p < 4; p++) {
        int row = 128 + bcol + p * 16 + i8 + l4 * 8;
        offB[p] = (uint32_t)(row * SKH + l3 * 8) * 2;
    }

    int s = 0;
    for (int it = 0; it < nk; it++) {
        CP_WAIT2();
        __syncthreads();
        const int j = it + 3;
        if (j < nk) {
            int sn = s + 3; if (sn >= ST_) sn -= ST_;
            load_stage(j, sn);
        }
        CP_COMMIT();

        const uint32_t sb = smem_base + (uint32_t)s * STAGE_BYTES;

        #pragma unroll
        for (int ks = 0; ks < 2; ks++) {
            const uint32_t kb = (uint32_t)(ks * 16 * 2);   // 16 halves per k-step
            uint32_t a[2][4], b[8][2];
            #pragma unroll
            for (int mf = 0; mf < 2; mf++) ldsm4(a[mf], sb + offA[mf] + kb);
            #pragma unroll
            for (int p = 0; p < 4; p++) {
                uint32_t r[4];
                ldsm4(r, sb + offB[p] + kb);
                b[2*p][0] = r[0]; b[2*p][1] = r[1];
                b[2*p+1][0] = r[2]; b[2*p+1][1] = r[3];
            }
            #pragma unroll
            for (int mf = 0; mf < 2; mf++)
                #pragma unroll
                for (int nf = 0; nf < 8; nf++)
                    mma_f16(acc[mf][nf], a[mf], b[nf]);
        }
        __syncthreads();
        if (++s == ST_) s = 0;
    }

    // epilogue
    long long cOff;
    int colBase, rowStride;
    if (SPLIT) {
        cOff = (long long)(n0 >> 10) * (long long)BSD;
        colBase = n0 & 1023;
        rowStride = 1024;
    } else {
        cOff = (long long)blockIdx.z * sC;
        colBase = n0;
        rowStride = N;
    }

    #pragma unroll
    for (int mf = 0; mf < 2; mf++) {
        #pragma unroll
        for (int nf = 0; nf < 8; nf++) {
            const int row  = m0 + arow + mf * 16 + g;
            const int colG = n0 + bcol + nf * 8 + q * 2;
            const int col  = colBase + bcol + nf * 8 + q * 2;
            float bx = 0.f, by = 0.f;
            if (bias) { bx = bias[colG]; by = bias[colG + 1]; }
            #pragma unroll
            for (int h = 0; h < 2; h++) {
                const int r = row + h * 8;
                float vx = acc[mf][nf][h * 2 + 0] * alpha + bx;
                float vy = acc[mf][nf][h * 2 + 1] * alpha + by;
                if (Rb) {
                    float2 rv = *(const float2*)&Rb[(long long)r * rowStride + col];
                    vx += rv.x; vy += rv.y;
                }
                if (OUTH) {
                    __half2* Cb = (__half2*)((__half*)Cv_ + cOff);
                    Cb[((long long)r * rowStride + col) >> 1] = __floats2half2_rn(vx, vy);
                } else {
                    float* Cb = (float*)Cv_ + cOff;
                    float2 v; v.x = vx; v.y = vy;
                    *(float2*)&Cb[(long long)r * rowStride + col] = v;
                }
            }
        }
    }
}

// ---------------- small utility kernels ----------------
__global__ void __launch_bounds__(256) convert_half_kernel(const float* __restrict__ in,
                                                           __half* __restrict__ out, int n4)
{
    int i = blockIdx.x * 256 + threadIdx.x;
    if (i < n4) {
        float4 v = ((const float4*)in)[i];
        __half2 h0 = __floats2half2_rn(v.x, v.y);
        __half2 h1 = __floats2half2_rn(v.z, v.w);
        ((__half2*)out)[i * 2 + 0] = h0;
        ((__half2*)out)[i * 2 + 1] = h1;
    }
}

__global__ void __launch_bounds__(256) pack_bias_kernel(
    const float* __restrict__ bq, const float* __restrict__ bv, float* __restrict__ o)
{
    int i = blockIdx.x * 256 + threadIdx.x;
    if (i < 3 * D_)
        o[i] = (i < D_) ? bq[i] : ((i < 2 * D_) ? 0.f : bv[i - 2 * D_]);
}

// f32 in -> half transposed out
__global__ void __launch_bounds__(256) transpose_f2h_kernel(
    const float* __restrict__ in, __half* __restrict__ out, int R, int C)
{
    __shared__ float tile[32][33];
    const int tx = threadIdx.x & 31, ty = threadIdx.x >> 5;
    const int c0 = blockIdx.x * 32, r0 = blockIdx.y * 32;
    #pragma unroll
    for (int j = 0; j < 4; j++)
        tile[ty + j * 8][tx] = in[(long long)(r0 + ty + j * 8) * C + c0 + tx];
    __syncthreads();
    #pragma unroll
    for (int j = 0; j < 4; j++)
        out[(long long)(c0 + ty + j * 8) * R + r0 + tx] = __float2half_rn(tile[tx][ty + j * 8]);
}

// half in -> half transposed out (batched)
__global__ void __launch_bounds__(256) transpose_h_kernel(
    const __half* __restrict__ in, __half* __restrict__ out,
    int R, int C, long long sIn, long long sOut)
{
    __shared__ __half tile[32][34];
    in  += (long long)blockIdx.z * sIn;
    out += (long long)blockIdx.z * sOut;
    const int tx = threadIdx.x & 31, ty = threadIdx.x >> 5;
    const int c0 = blockIdx.x * 32, r0 = blockIdx.y * 32;
    #pragma unroll
    for (int j = 0; j < 4; j++)
        tile[ty + j * 8][tx] = in[(long long)(r0 + ty + j * 8) * C + c0 + tx];
    __syncthreads();
    #pragma unroll
    for (int j = 0; j < 4; j++)
        out[(long long)(c0 + ty + j * 8) * R + r0 + tx] = tile[tx][ty + j * 8];
}

// ---------------- reductions ----------------
__device__ __forceinline__ float warpSum(float v) {
    #pragma unroll
    for (int o = 16; o > 0; o >>= 1) v += __shfl_xor_sync(0xffffffffu, v, o);
    return v;
}
__device__ __forceinline__ float warpMax(float v) {
    #pragma unroll
    for (int o = 16; o > 0; o >>= 1) v = fmaxf(v, __shfl_xor_sync(0xffffffffu, v, o));
    return v;
}
__device__ __forceinline__ float blockSum(float v, float* red) {
    int t = threadIdx.x, lane = t & 31, w = t >> 5;
    v = warpSum(v);
    if (lane == 0) red[w] = v;
    __syncthreads();
    if (w == 0) {
        float x = (lane < 8) ? red[lane] : 0.f;
        x = warpSum(x);
        if (lane == 0) red[0] = x;
    }
    __syncthreads();
    float r = red[0];
    __syncthreads();
    return r;
}
__device__ __forceinline__ float blockMax(float v, float* red) {
    int t = threadIdx.x, lane = t & 31, w = t >> 5;
    v = warpMax(v);
    if (lane == 0) red[w] = v;
    __syncthreads();
    if (w == 0) {
        float x = (lane < 8) ? red[lane] : -1e30f;
        x = warpMax(x);
        if (lane == 0) red[0] = x;
    }
    __syncthreads();
    float r = red[0];
    __syncthreads();
    return r;
}

// ---------------- grouped conv1d (K=3, pad=1) + LayerNorm (f32 exact) ----------------
__global__ void __launch_bounds__(256) conv_ln_kernel(
    const float* __restrict__ x, const float* __restrict__ cw,
    const float* __restrict__ cb, const float* __restrict__ gamma,
    const float* __restrict__ beta)
{
    __shared__ float xs[6][D_];
    __shared__ float red[32];

    const int t  = threadIdx.x;
    const int s0 = blockIdx.x * 4;
    const int b  = blockIdx.y;
    const float* xb = x + (size_t)b * S_ * D_;

    #pragma unroll
    for (int r = 0; r < 6; r++) {
        int sr = s0 - 1 + r;
        if (sr >= 0 && sr < S_) {
            for (int i = t; i < D_; i += 256) xs[r][i] = xb[(size_t)sr * D_ + i];
        } else {
            for (int i = t; i < D_; i += 256) xs[r][i] = 0.f;
        }
    }
    __syncthreads();

    float acc[4][4];
    #pragma unroll
    for (int dd = 0; dd < 4; dd++) {
        const int d  = t * 4 + dd;
        const int gb = (d >> 6) << 6;
        const float* wp = cw + (size_t)d * GC_ * 3;
        float a0 = cb[d], a1 = a0, a2 = a0, a3 = a0;
        #pragma unroll 8
        for (int c = 0; c < GC_; c++) {
            float w0 = wp[c * 3 + 0], w1 = wp[c * 3 + 1], w2 = wp[c * 3 + 2];
            float x0 = xs[0][gb + c], x1 = xs[1][gb + c], x2 = xs[2][gb + c];
            float x3 = xs[3][gb + c], x4 = xs[4][gb + c], x5 = xs[5][gb + c];
            a0 += w0 * x0 + w1 * x1 + w2 * x2;
            a1 += w0 * x1 + w1 * x2 + w2 * x3;
            a2 += w0 * x2 + w1 * x3 + w2 * x4;
            a3 += w0 * x3 + w1 * x4 + w2 * x5;
        }
        acc[dd][0] = a0; acc[dd][1] = a1; acc[dd][2] = a2; acc[dd][3] = a3;
    }

    const float4 gv = *(const float4*)&gamma[t * 4];
    const float4 bvv = *(const float4*)&beta[t * 4];
    const float gvl[4] = {gv.x, gv.y, gv.z, gv.w};
    const float bvl[4] = {bvv.x, bvv.y, bvv.z, bvv.w};

    for (int p = 0; p < 4; p++) {
        float s = acc[0][p] + acc[1][p] + acc[2][p] + acc[3][p];
        float mean = blockSum(s, red) * (1.f / D_);
        float sq = 0.f;
        #pragma unroll
        for (int dd = 0; dd < 4; dd++) { float dl = acc[dd][p] - mean; sq += dl * dl; }
        float var = blockSum(sq, red) * (1.f / (D_ - 1));
        float inv = 1.f / (sqrtf(var) + EPS_);
        float* out = g_Cv + ((size_t)b * S_ + s0 + p) * D_;
        float4 ov;
        ov.x = gvl[0] * (acc[0][p] - mean) * inv + bvl[0];
        ov.y = gvl[1] * (acc[1][p] - mean) * inv + bvl[1];
        ov.z = gvl[2] * (acc[2][p] - mean) * inv + bvl[2];
        ov.w = gvl[3] * (acc[3][p] - mean) * inv + bvl[3];
        *(float4*)&out[t * 4] = ov;
    }
}

// ---------------- row softmax: f32 scores -> half probs ----------------
__global__ void __launch_bounds__(256) softmax_kernel()
{
    __shared__ float red[32];
    const int t = threadIdx.x;
    const size_t rbase = ((size_t)blockIdx.y * S_ + blockIdx.x) * S_;
    const float* row = g_Sc + rbase;
    __half* prow = g_Ph + rbase;

    float v[8];
    float m = -1e30f;
    #pragma unroll
    for (int j = 0; j < 8; j++) { v[j] = row[t + j * 256]; m = fmaxf(m, v[j]); }
    m = blockMax(m, red);

    float sum = 0.f;
    #pragma unroll
    for (int j = 0; j < 8; j++) { v[j] = __expf(v[j] - m); sum += v[j]; }
    sum = blockSum(sum, red);
    float inv = 1.f / sum;
    #pragma unroll
    for (int j = 0; j < 8; j++) prow[t + j * 256] = __float2half_rn(v[j] * inv);
}

// ---------------- combined = LN(conv_ln + attn_out) -> half g_Ch ----------------
__global__ void __launch_bounds__(256) add_ln_kernel(
    const float* __restrict__ gamma, const float* __restrict__ beta)
{
    __shared__ float red[32];
    const int t = threadIdx.x;
    const size_t row = ((size_t)blockIdx.y * S_ + blockIdx.x) * D_;

    float v[4];
    float s = 0.f;
    #pragma unroll
    for (int j = 0; j < 4; j++) {
        int i = t + j * 256;
        v[j] = g_Cv[row + i] + g_Ao[row + i];
        s += v[j];
    }
    float mean = blockSum(s, red) * (1.f / D_);
    float sq = 0.f;
    #pragma unroll
    for (int j = 0; j < 4; j++) { float dl = v[j] - mean; sq += dl * dl; }
    float var = blockSum(sq, red) * (1.f / (D_ - 1));
    float inv = 1.f / (sqrtf(var) + EPS_);
    #pragma unroll
    for (int j = 0; j < 4; j++) {
        int i = t + j * 256;
        g_Ch[row + i] = __float2half_rn(gamma[i] * (v[j] - mean) * inv + beta[i]);
    }
}

// ---------------- launch ----------------
extern "C" void kernel_launch(void* const* d_in, const int* in_sizes, int n_in,
                              void* d_out, int out_size)
{
    const float* x     = (const float*)d_in[0];
    const float* Wq    = (const float*)d_in[1];
    const float* bq    = (const float*)d_in[2];
    const float* Wk    = (const float*)d_in[3];
    const float* Wv    = (const float*)d_in[4];
    const float* bv    = (const float*)d_in[5];
    const float* cw    = (const float*)d_in[6];
    const float* cb    = (const float*)d_in[7];
    const float* gamma = (const float*)d_in[8];
    const float* beta  = (const float*)d_in[9];
    const float* Wo    = (const float*)d_in[10];
    const float* bo    = (const float*)d_in[11];
    float* out = (float*)d_out;

    __half *pXh, *pWth, *pQKVh, *pVth, *pPh, *pCh;
    float  *pSc, *pCv, *pAo, *pBias;
    cudaGetSymbolAddress((void**)&pXh,   g_Xh);
    cudaGetSymbolAddress((void**)&pWth,  g_Wth);
    cudaGetSymbolAddress((void**)&pQKVh, g_QKVh);
    cudaGetSymbolAddress((void**)&pVth,  g_Vth);
    cudaGetSymbolAddress((void**)&pPh,   g_Ph);
    cudaGetSymbolAddress((void**)&pCh,   g_Ch);
    cudaGetSymbolAddress((void**)&pSc,   g_Sc);
    cudaGetSymbolAddress((void**)&pCv,   g_Cv);
    cudaGetSymbolAddress((void**)&pAo,   g_Ao);
    cudaGetSymbolAddress((void**)&pBias, g_bias);

    cudaFuncSetAttribute(mma_gemm_h<0,0>, cudaFuncAttributeMaxDynamicSharedMemorySize, SMEM_DYN);
    cudaFuncSetAttribute(mma_gemm_h<1,0>, cudaFuncAttributeMaxDynamicSharedMemorySize, SMEM_DYN);
    cudaFuncSetAttribute(mma_gemm_h<1,1>, cudaFuncAttributeMaxDynamicSharedMemorySize, SMEM_DYN);

    const int M = B_ * S_;
    const long long sSD = (long long)S_ * D_;
    const long long sSS = (long long)S_ * S_;
    const long long DD  = (long long)D_ * D_;

    __half* pQh = pQKVh;
    __half* pKh = pQKVh + BSD;
    __half* pVh = pQKVh + 2 * BSD;

    // x -> half; pack bias
    const int n4 = (B_ * S_ * D_) / 4;
    convert_half_kernel<<<n4 / 256, 256>>>(x, pXh, n4);
    pack_bias_kernel<<<12, 256>>>(bq, bv, pBias);

    // weights: transpose f32 -> half
    dim3 tb(256), tgW(D_ / 32, D_ / 32, 1);
    transpose_f2h_kernel<<<tgW, tb>>>(Wq, pWth + 0 * DD, D_, D_);
    transpose_f2h_kernel<<<tgW, tb>>>(Wk, pWth + 1 * DD, D_, D_);
    transpose_f2h_kernel<<<tgW, tb>>>(Wv, pWth + 2 * DD, D_, D_);
    transpose_f2h_kernel<<<tgW, tb>>>(Wo, pWth + 3 * DD, D_, D_);

    // fused QKV: [8192,1024]h @ [3072,1024]h^T -> Q|K|V half
    dim3 gblk(256);
    mma_gemm_h<1,1><<<dim3(3 * D_ / BN, M / BM, 1), gblk, SMEM_DYN>>>(
        pXh, pWth, pBias, nullptr, pQKVh, M, 3 * D_, D_, 0, 0, 0, 1.f);

    // grouped conv + LN (exact f32 x)
    conv_ln_kernel<<<dim3(S_ / 4, B_), dim3(256)>>>(x, cw, cb, gamma, beta);

    // V^T per batch (half)
    transpose_h_kernel<<<dim3(D_ / 32, S_ / 32, B_), tb>>>(pVh, pVth, S_, D_, sSD, sSD);

    // scores = Q @ K^T * (1/32) -> f32
    mma_gemm_h<0,0><<<dim3(S_ / BN, S_ / BM, B_), gblk, SMEM_DYN>>>(
        pQh, pKh, nullptr, nullptr, pSc, S_, S_, D_, sSD, sSD, sSS, 0.03125f);

    // softmax -> half probs
    softmax_kernel<<<dim3(S_, B_), dim3(256)>>>();

    // attn_out = P @ Vt^T -> f32
    mma_gemm_h<0,0><<<dim3(D_ / BN, S_ / BM, B_), gblk, SMEM_DYN>>>(
        pPh, pVth, nullptr, nullptr, pAo, S_, D_, S_, sSS, sSD, sSD, 1.f);

    // combined = LN(conv_ln + attn_out) -> half
    add_ln_kernel<<<dim3(S_, B_), dim3(256)>>>(gamma, beta);

    // out = combined @ Wo^T + bo + x (f32 out, exact residual)
    mma_gemm_h<0,0><<<dim3(D_ / BN, M / BM, 1), gblk, SMEM_DYN>>>(
        pCh, pWth + 3 * DD, bo, x, out, M, D_, D_, 0, 0, 0, 1.f);
}

// round 12
// speedup vs baseline: 1.3510x; 1.3510x over previous
#include <cuda_runtime.h>
#include <math.h>
#include <stdint.h>

#define B_ 4
#define S_ 2048
#define D_ 1024
#define GC_ 64
#define EPS_ 1e-6f

// GEMM tiling
#define BM 128
#define BN 128
#define BK 32
#define ST_ 3
#define ASTRIDE 36                        // 32 + 4 pad floats
#define STAGE_F (2 * 128 * ASTRIDE)       // floats per stage (A + B)
#define STAGE_BYTES (STAGE_F * 4)
#define SMEM_DYN (ST_ * STAGE_BYTES)

#define BSD ((size_t)B_ * S_ * D_)

// ---------------- scratch (device globals: allocation-guard safe) ----------------
static __device__ __align__(256) float g_Xt [BSD];          // tf32-rounded x
static __device__ __align__(256) float g_QKV[3 * BSD];      // Q | K | V
static __device__ __align__(256) float g_Vt [BSD];
static __device__ __align__(256) float g_Cv [BSD];
static __device__ __align__(256) float g_Ao [BSD];
static __device__ __align__(256) float g_Sc [(size_t)B_*S_*S_];
static __device__ __align__(256) float g_Wt [(size_t)4*D_*D_];  // Wq^T|Wk^T|Wv^T|Wo^T
static __device__ __align__(256) float g_bias[3 * D_];

// ---------------- helpers ----------------
__device__ __forceinline__ uint32_t smem_u32(const void* p) {
    uint32_t a;
    asm("{ .reg .u64 t; cvta.to.shared.u64 t, %1; cvt.u32.u64 %0, t; }" : "=r"(a) : "l"(p));
    return a;
}
__device__ __forceinline__ float to_tf32(float x) {
    uint32_t o;
    asm("cvt.rna.tf32.f32 %0, %1;" : "=r"(o) : "f"(x));
    return __uint_as_float(o);
}
__device__ __forceinline__ void cpa16(uint32_t s, const float* g) {
    asm volatile("cp.async.cg.shared.global [%0], [%1], 16;" :: "r"(s), "l"(g));
}
#define CP_COMMIT() asm volatile("cp.async.commit_group;" ::: "memory")
#define CP_WAIT1()  asm volatile("cp.async.wait_group 1;"  ::: "memory")

__device__ __forceinline__ void ldsm4(uint32_t* r, uint32_t a) {
    asm volatile("ldmatrix.sync.aligned.m8n8.x4.shared.b16 {%0,%1,%2,%3}, [%4];"
        : "=r"(r[0]), "=r"(r[1]), "=r"(r[2]), "=r"(r[3]) : "r"(a));
}
__device__ __forceinline__ void mma_tf32(float* c, const uint32_t* a, const uint32_t* b) {
    asm volatile(
        "mma.sync.aligned.m16n8k8.row.col.f32.tf32.tf32.f32 "
        "{%0,%1,%2,%3}, {%4,%5,%6,%7}, {%8,%9}, {%0,%1,%2,%3};"
        : "+f"(c[0]), "+f"(c[1]), "+f"(c[2]), "+f"(c[3])
        : "r"(a[0]), "r"(a[1]), "r"(a[2]), "r"(a[3]), "r"(b[0]), "r"(b[1]));
}

// ---------------- mma.sync tf32 GEMM: C = alpha*A@B^T (+bias) (+res) ----------------
// A [M,K] row-major, B [N,K] row-major (pre-rounded tf32).
// 128x128x32 CTA tile, 128 threads, 4 warps (2m x 2n), warp tile 64x64.
// 3-stage cp.async ring, 2 CTAs/SM.
// SPLIT: output columns 1024-segmented into 3 consecutive [M,1024] buffers.
template <int CVT, int SPLIT>
__global__ void __launch_bounds__(128, 2) mma_gemm(
    const float* __restrict__ A, const float* __restrict__ B,
    const float* __restrict__ bias, const float* __restrict__ res,
    float* __restrict__ C, int M, int N, int Kd,
    long long sA, long long sB, long long sC, float alpha)
{
    extern __shared__ __align__(128) float smemf[];
    const uint32_t smem_base = smem_u32(smemf);

    const int t    = threadIdx.x;
    const int wid  = t >> 5;
    const int lane = t & 31;
    const int g    = lane >> 2;
    const int q    = lane & 3;
    const int wm   = wid & 1;         // warp m 0..1
    const int wn   = wid >> 1;        // warp n 0..1
    const int m0 = blockIdx.y * BM, n0 = blockIdx.x * BN;

    const float* Ab = A + (long long)blockIdx.z * sA;
    const float* Bb = B + (long long)blockIdx.z * sB;
    const float* Rb = res ? res + (long long)blockIdx.z * sC : nullptr;

    float acc[4][8][4];
    #pragma unroll
    for (int i = 0; i < 4; i++)
        #pragma unroll
        for (int j = 0; j < 8; j++)
            #pragma unroll
            for (int k = 0; k < 4; k++) acc[i][j][k] = 0.f;

    const int nk = Kd / BK;

    auto load_stage = [&](int j, int s) {
        const int k0 = j * BK;
        const uint32_t sb = smem_base + (uint32_t)s * STAGE_BYTES;
        #pragma unroll
        for (int i = 0; i < 8; i++) {
            int idx = t + i * 128;
            int row = idx >> 3, c4 = idx & 7;
            cpa16(sb + (uint32_t)(row * ASTRIDE + c4 * 4) * 4,
                  Ab + (long long)(m0 + row) * Kd + k0 + c4 * 4);
        }
        #pragma unroll
        for (int i = 0; i < 8; i++) {
            int idx = t + i * 128;
            int row = idx >> 3, c4 = idx & 7;
            cpa16(sb + (uint32_t)(128 * ASTRIDE + row * ASTRIDE + c4 * 4) * 4,
                  Bb + (long long)(n0 + row) * Kd + k0 + c4 * 4);
        }
    };

    load_stage(0, 0); CP_COMMIT();
    load_stage(1, 1); CP_COMMIT();

    const int arow = wm * 64;
    const int bcol = wn * 64;

    // ldmatrix lane address offsets (bytes within stage A / B regions)
    const int i8 = lane & 7, qd = lane >> 3;
    uint32_t offA[4], offB[4];
    #pragma unroll
    for (int mf = 0; mf < 4; mf++) {
        int row = arow + mf * 16 + i8 + (qd & 1) * 8;
        offA[mf] = (uint32_t)(row * ASTRIDE + (qd >> 1) * 4) * 4;
    }
    #pragma unroll
    for (int p = 0; p < 4; p++) {
        int row = bcol + p * 16 + i8 + (qd >> 1) * 8;
        offB[p] = (uint32_t)(row * ASTRIDE + (qd & 1) * 4) * 4;
    }

    int s = 0;
    for (int it = 0; it < nk; it++) {
        CP_WAIT1();
        __syncthreads();
        const int j = it + 2;
        if (j < nk) {
            int sn = s + 2; if (sn >= ST_) sn -= ST_;
            load_stage(j, sn);
        }
        CP_COMMIT();

        const uint32_t sAb = smem_base + (uint32_t)s * STAGE_BYTES;
        const uint32_t sBb = sAb + (uint32_t)(128 * ASTRIDE * 4);

        #pragma unroll
        for (int ks = 0; ks < 4; ks++) {
            const uint32_t kb = (uint32_t)(ks * 8 * 4);
            uint32_t a[4][4], b[8][2];
            #pragma unroll
            for (int mf = 0; mf < 4; mf++) ldsm4(a[mf], sAb + offA[mf] + kb);
            #pragma unroll
            for (int p = 0; p < 4; p++) ldsm4(&b[2 * p][0], sBb + offB[p] + kb);
            #pragma unroll
            for (int mf = 0; mf < 4; mf++)
                #pragma unroll
                for (int nf = 0; nf < 8; nf++)
                    mma_tf32(acc[mf][nf], a[mf], b[nf]);
        }
        __syncthreads();
        if (++s == ST_) s = 0;
    }

    // epilogue
    float* Cb;
    int colBase, rowStride;
    if (SPLIT) {
        Cb = C + (long long)(n0 >> 10) * (long long)(B_ * (size_t)S_ * D_);
        colBase = n0 & 1023;
        rowStride = 1024;
    } else {
        Cb = C + (long long)blockIdx.z * sC;
        colBase = n0;
        rowStride = N;
    }

    #pragma unroll
    for (int mf = 0; mf < 4; mf++) {
        #pragma unroll
        for (int nf = 0; nf < 8; nf++) {
            const int row  = m0 + arow + mf * 16 + g;
            const int colG = n0 + bcol + nf * 8 + q * 2;     // bias index
            const int col  = colBase + bcol + nf * 8 + q * 2;
            float bx = 0.f, by = 0.f;
            if (bias) { bx = bias[colG]; by = bias[colG + 1]; }
            #pragma unroll
            for (int h = 0; h < 2; h++) {
                const int r = row + h * 8;
                float vx = acc[mf][nf][h * 2 + 0] * alpha + bx;
                float vy = acc[mf][nf][h * 2 + 1] * alpha + by;
                if (Rb) {
                    float2 rv = *(const float2*)&Rb[(long long)r * rowStride + col];
                    vx += rv.x; vy += rv.y;
                }
                if (CVT) { vx = to_tf32(vx); vy = to_tf32(vy); }
                float2 v; v.x = vx; v.y = vy;
                *(float2*)&Cb[(long long)r * rowStride + col] = v;
            }
        }
    }
}

// ---------------- small utility kernels ----------------
__global__ void __launch_bounds__(256) convert_kernel(const float* __restrict__ in,
                                                     float* __restrict__ out, int n4)
{
    int i = blockIdx.x * 256 + threadIdx.x;
    if (i < n4) {
        float4 v = ((const float4*)in)[i];
        v.x = to_tf32(v.x); v.y = to_tf32(v.y);
        v.z = to_tf32(v.z); v.w = to_tf32(v.w);
        ((float4*)out)[i] = v;
    }
}

__global__ void __launch_bounds__(256) pack_bias_kernel(
    const float* __restrict__ bq, const float* __restrict__ bv, float* __restrict__ o)
{
    int i = blockIdx.x * 256 + threadIdx.x;
    if (i < 3 * D_)
        o[i] = (i < D_) ? bq[i] : ((i < 2 * D_) ? 0.f : bv[i - 2 * D_]);
}

__global__ void __launch_bounds__(256) transpose_kernel(
    const float* __restrict__ in, float* __restrict__ out,
    int R, int C, long long sIn, long long sOut)
{
    __shared__ float tile[32][33];
    in  += (long long)blockIdx.z * sIn;
    out += (long long)blockIdx.z * sOut;
    const int tx = threadIdx.x & 31, ty = threadIdx.x >> 5;
    const int c0 = blockIdx.x * 32, r0 = blockIdx.y * 32;
    #pragma unroll
    for (int j = 0; j < 4; j++)
        tile[ty + j * 8][tx] = in[(long long)(r0 + ty + j * 8) * C + c0 + tx];
    __syncthreads();
    #pragma unroll
    for (int j = 0; j < 4; j++)
        out[(long long)(c0 + ty + j * 8) * R + r0 + tx] = to_tf32(tile[tx][ty + j * 8]);
}

// ---------------- reductions ----------------
__device__ __forceinline__ float warpSum(float v) {
    #pragma unroll
    for (int o = 16; o > 0; o >>= 1) v += __shfl_xor_sync(0xffffffffu, v, o);
    return v;
}
__device__ __forceinline__ float warpMax(float v) {
    #pragma unroll
    for (int o = 16; o > 0; o >>= 1) v = fmaxf(v, __shfl_xor_sync(0xffffffffu, v, o));
    return v;
}
__device__ __forceinline__ float blockSum(float v, float* red) {
    int t = threadIdx.x, lane = t & 31, w = t >> 5;
    v = warpSum(v);
    if (lane == 0) red[w] = v;
    __syncthreads();
    if (w == 0) {
        float x = (lane < 8) ? red[lane] : 0.f;
        x = warpSum(x);
        if (lane == 0) red[0] = x;
    }
    __syncthreads();
    float r = red[0];
    __syncthreads();
    return r;
}
__device__ __forceinline__ float blockMax(float v, float* red) {
    int t = threadIdx.x, lane = t & 31, w = t >> 5;
    v = warpMax(v);
    if (lane == 0) red[w] = v;
    __syncthreads();
    if (w == 0) {
        float x = (lane < 8) ? red[lane] : -1e30f;
        x = warpMax(x);
        if (lane == 0) red[0] = x;
    }
    __syncthreads();
    float r = red[0];
    __syncthreads();
    return r;
}

// ---------------- grouped conv1d (K=3, pad=1) + LayerNorm ----------------
__global__ void __launch_bounds__(256) conv_ln_kernel(
    const float* __restrict__ x, const float* __restrict__ cw,
    const float* __restrict__ cb, const float* __restrict__ gamma,
    const float* __restrict__ beta)
{
    __shared__ float xs[6][D_];
    __shared__ float red[32];

    const int t  = threadIdx.x;
    const int s0 = blockIdx.x * 4;
    const int b  = blockIdx.y;
    const float* xb = x + (size_t)b * S_ * D_;

    #pragma unroll
    for (int r = 0; r < 6; r++) {
        int sr = s0 - 1 + r;
        if (sr >= 0 && sr < S_) {
            for (int i = t; i < D_; i += 256) xs[r][i] = xb[(size_t)sr * D_ + i];
        } else {
            for (int i = t; i < D_; i += 256) xs[r][i] = 0.f;
        }
    }
    __syncthreads();

    float acc[4][4];
    #pragma unroll
    for (int dd = 0; dd < 4; dd++) {
        const int d  = t * 4 + dd;
        const int gb = (d >> 6) << 6;
        const float* wp = cw + (size_t)d * GC_ * 3;
        float a0 = cb[d], a1 = a0, a2 = a0, a3 = a0;
        #pragma unroll 8
        for (int c = 0; c < GC_; c++) {
            float w0 = wp[c * 3 + 0], w1 = wp[c * 3 + 1], w2 = wp[c * 3 + 2];
            float x0 = xs[0][gb + c], x1 = xs[1][gb + c], x2 = xs[2][gb + c];
            float x3 = xs[3][gb + c], x4 = xs[4][gb + c], x5 = xs[5][gb + c];
            a0 += w0 * x0 + w1 * x1 + w2 * x2;
            a1 += w0 * x1 + w1 * x2 + w2 * x3;
            a2 += w0 * x2 + w1 * x3 + w2 * x4;
            a3 += w0 * x3 + w1 * x4 + w2 * x5;
        }
        acc[dd][0] = a0; acc[dd][1] = a1; acc[dd][2] = a2; acc[dd][3] = a3;
    }

    const float4 gv = *(const float4*)&gamma[t * 4];
    const float4 bvv = *(const float4*)&beta[t * 4];
    const float gvl[4] = {gv.x, gv.y, gv.z, gv.w};
    const float bvl[4] = {bvv.x, bvv.y, bvv.z, bvv.w};

    for (int p = 0; p < 4; p++) {
        float s = acc[0][p] + acc[1][p] + acc[2][p] + acc[3][p];
        float mean = blockSum(s, red) * (1.f / D_);
        float sq = 0.f;
        #pragma unroll
        for (int dd = 0; dd < 4; dd++) { float dl = acc[dd][p] - mean; sq += dl * dl; }
        float var = blockSum(sq, red) * (1.f / (D_ - 1));
        float inv = 1.f / (sqrtf(var) + EPS_);
        float* out = g_Cv + ((size_t)b * S_ + s0 + p) * D_;
        float4 ov;
        ov.x = gvl[0] * (acc[0][p] - mean) * inv + bvl[0];
        ov.y = gvl[1] * (acc[1][p] - mean) * inv + bvl[1];
        ov.z = gvl[2] * (acc[2][p] - mean) * inv + bvl[2];
        ov.w = gvl[3] * (acc[3][p] - mean) * inv + bvl[3];
        *(float4*)&out[t * 4] = ov;
    }
}

// ---------------- row softmax (writes tf32-rounded probs) ----------------
__global__ void __launch_bounds__(256) softmax_kernel()
{
    __shared__ float red[32];
    const int t = threadIdx.x;
    float* row = g_Sc + ((size_t)blockIdx.y * S_ + blockIdx.x) * S_;

    float v[8];
    float m = -1e30f;
    #pragma unroll
    for (int j = 0; j < 8; j++) { v[j] = row[t + j * 256]; m = fmaxf(m, v[j]); }
    m = blockMax(m, red);

    float sum = 0.f;
    #pragma unroll
    for (int j = 0; j < 8; j++) { v[j] = __expf(v[j] - m); sum += v[j]; }
    sum = blockSum(sum, red);
    float inv = 1.f / sum;
    #pragma unroll
    for (int j = 0; j < 8; j++) row[t + j * 256] = to_tf32(v[j] * inv);
}

// ---------------- combined = LN(conv_ln + attn_out) -> g_Cv (tf32-rounded) ------
__global__ void __launch_bounds__(256) add_ln_kernel(
    const float* __restrict__ gamma, const float* __restrict__ beta)
{
    __shared__ float red[32];
    const int t = threadIdx.x;
    const size_t row = ((size_t)blockIdx.y * S_ + blockIdx.x) * D_;

    float v[4];
    float s = 0.f;
    #pragma unroll
    for (int j = 0; j < 4; j++) {
        int i = t + j * 256;
        v[j] = g_Cv[row + i] + g_Ao[row + i];
        s += v[j];
    }
    float mean = blockSum(s, red) * (1.f / D_);
    float sq = 0.f;
    #pragma unroll
    for (int j = 0; j < 4; j++) { float dl = v[j] - mean; sq += dl * dl; }
    float var = blockSum(sq, red) * (1.f / (D_ - 1));
    float inv = 1.f / (sqrtf(var) + EPS_);
    #pragma unroll
    for (int j = 0; j < 4; j++) {
        int i = t + j * 256;
        g_Cv[row + i] = to_tf32(gamma[i] * (v[j] - mean) * inv + beta[i]);
    }
}

// ---------------- launch ----------------
extern "C" void kernel_launch(void* const* d_in, const int* in_sizes, int n_in,
                              void* d_out, int out_size)
{
    const float* x     = (const float*)d_in[0];
    const float* Wq    = (const float*)d_in[1];
    const float* bq    = (const float*)d_in[2];
    const float* Wk    = (const float*)d_in[3];
    const float* Wv    = (const float*)d_in[4];
    const float* bv    = (const float*)d_in[5];
    const float* cw    = (const float*)d_in[6];
    const float* cb    = (const float*)d_in[7];
    const float* gamma = (const float*)d_in[8];
    const float* beta  = (const float*)d_in[9];
    const float* Wo    = (const float*)d_in[10];
    const float* bo    = (const float*)d_in[11];
    float* out = (float*)d_out;

    float *pXt, *pQKV, *pVt, *pC, *pA, *pS, *pWt, *pBias;
    cudaGetSymbolAddress((void**)&pXt,  g_Xt);
    cudaGetSymbolAddress((void**)&pQKV, g_QKV);
    cudaGetSymbolAddress((void**)&pVt,  g_Vt);
    cudaGetSymbolAddress((void**)&pC,   g_Cv);
    cudaGetSymbolAddress((void**)&pA,   g_Ao);
    cudaGetSymbolAddress((void**)&pS,   g_Sc);
    cudaGetSymbolAddress((void**)&pWt,  g_Wt);
    cudaGetSymbolAddress((void**)&pBias,g_bias);

    cudaFuncSetAttribute(mma_gemm<0,0>, cudaFuncAttributeMaxDynamicSharedMemorySize, SMEM_DYN);
    cudaFuncSetAttribute(mma_gemm<1,0>, cudaFuncAttributeMaxDynamicSharedMemorySize, SMEM_DYN);
    cudaFuncSetAttribute(mma_gemm<1,1>, cudaFuncAttributeMaxDynamicSharedMemorySize, SMEM_DYN);

    const int M = B_ * S_;
    const long long sSD = (long long)S_ * D_;
    const long long sSS = (long long)S_ * S_;
    const long long DD  = (long long)D_ * D_;

    float* pQ = pQKV;
    float* pK = pQKV + BSD;
    float* pV = pQKV + 2 * BSD;

    // tf32-round x; pack bias
    const int n4 = (B_ * S_ * D_) / 4;
    convert_kernel<<<n4 / 256, 256>>>(x, pXt, n4);
    pack_bias_kernel<<<12, 256>>>(bq, bv, pBias);

    // transpose + round weights
    dim3 tb(256), tgW(D_ / 32, D_ / 32, 1);
    transpose_kernel<<<tgW, tb>>>(Wq, pWt + 0 * DD, D_, D_, 0, 0);
    transpose_kernel<<<tgW, tb>>>(Wk, pWt + 1 * DD, D_, D_, 0, 0);
    transpose_kernel<<<tgW, tb>>>(Wv, pWt + 2 * DD, D_, D_, 0, 0);
    transpose_kernel<<<tgW, tb>>>(Wo, pWt + 3 * DD, D_, D_, 0, 0);

    // fused QKV projection: [8192,1024] @ [3072,1024]^T -> Q|K|V (all tf32-rounded)
    dim3 gblk(128);
    mma_gemm<1,1><<<dim3(3 * D_ / BN, M / BM, 1), gblk, SMEM_DYN>>>(
        pXt, pWt, pBias, nullptr, pQKV, M, 3 * D_, D_, 0, 0, 0, 1.f);

    // grouped conv + LN (uses exact x)
    conv_ln_kernel<<<dim3(S_ / 4, B_), dim3(256)>>>(x, cw, cb, gamma, beta);

    // V^T per batch (rounded)
    transpose_kernel<<<dim3(D_ / 32, S_ / 32, B_), tb>>>(pV, pVt, S_, D_, sSD, sSD);

    // scores = Q @ K^T * (1/32)
    mma_gemm<0,0><<<dim3(S_ / BN, S_ / BM, B_), gblk, SMEM_DYN>>>(
        pQ, pK, nullptr, nullptr, pS, S_, S_, D_, sSD, sSD, sSS, 0.03125f);

    // softmax rows (rounded probs)
    softmax_kernel<<<dim3(S_, B_), dim3(256)>>>();

    // attn_out = P @ Vt^T = P @ V
    mma_gemm<0,0><<<dim3(D_ / BN, S_ / BM, B_), gblk, SMEM_DYN>>>(
        pS, pVt, nullptr, nullptr, pA, S_, D_, S_, sSS, sSD, sSD, 1.f);

    // combined = LN(conv_ln + attn_out) (rounded)
    add_ln_kernel<<<dim3(S_, B_), dim3(256)>>>(gamma, beta);

    // out = combined @ Wo^T + bo + x (exact residual)
    mma_gemm<0,0><<<dim3(D_ / BN, M / BM, 1), gblk, SMEM_DYN>>>(
        pC, pWt + 3 * DD, bo, x, out, M, D_, D_, 0, 0, 0, 1.f);
}